// round 2
// baseline (speedup 1.0000x reference)
#include <cuda_runtime.h>
#include <cstddef>

// UpsampleUpFIRDn: x (8,64,256,256) f32 -> out (8,64,512,512) f32, up=2, 4x4 FIR.
// Parity reduction (verified in R1):
//  out[2m][2n]     = k11*x[m][n]  + k13*x[m][n-1]  + k31*x[m-1][n] + k33*x[m-1][n-1]
//  out[2m][2n+1]   = k12*x[m][n]  + k10*x[m][n+1]  + k32*x[m-1][n] + k30*x[m-1][n+1]
//  out[2m+1][2n]   = k21*x[m][n]  + k23*x[m][n-1]  + k01*x[m+1][n] + k03*x[m+1][n-1]
//  out[2m+1][2n+1] = k22*x[m][n]  + k20*x[m][n+1]  + k02*x[m+1][n] + k00*x[m+1][n+1]
//
// R2: vectorized. Thread = 4 input cols x 4 input rows -> 8x8 output block.
//  - smem tile 34 rows x 136 cols, col c <-> global col n0-4+c so aligned
//    global float4 loads land on 16B-aligned STS.128 at col 4+4j.
//  - compute: 3x LDS.128 per row (conflict-free), rolling row registers
//    (1 new row per iteration), STG.128 streaming stores (__stcs).

#define IH 256
#define IW 256
#define OW 512

#define TILE_X 128      // input cols per block (32 threads x 4 cols)
#define TILE_Y 32       // input rows per block (8 groups x 4 rows)
#define SM_ROWS 34      // TILE_Y + 2 halo
#define SM_STRIDE 136   // 4 (left pad) + 128 + 4 (right pad), %4==0 for .128 align

__constant__ float c_k[16];

// Extract the 6 floats x[n-1..n+4] for one smem row via 3 aligned LDS.128.
#define LOADROW(dst, rowptr, tx4)                                   \
    {                                                               \
        float4 A = *(const float4*)((rowptr) + (tx4));              \
        float4 B = *(const float4*)((rowptr) + (tx4) + 4);          \
        float4 C = *(const float4*)((rowptr) + (tx4) + 8);          \
        dst[0] = A.w; dst[1] = B.x; dst[2] = B.y;                   \
        dst[3] = B.z; dst[4] = B.w; dst[5] = C.x;                   \
    }

__global__ __launch_bounds__(256)
void upfirdn2x_kernel(const float* __restrict__ x, float* __restrict__ out)
{
    __shared__ float s[SM_ROWS][SM_STRIDE];

    const int tid  = threadIdx.x;
    const int n0   = blockIdx.x * TILE_X;   // input col origin
    const int m0   = blockIdx.y * TILE_Y;   // input row origin
    const int p    = blockIdx.z;            // plane (N*C)

    const float* xp = x + (size_t)p * (IH * IW);
    float* op = out + (size_t)p * (OW * (size_t)OW);

    // ---- load haloed tile: smem col c <-> global col n0-4+c ----
    {
        const int warp = tid >> 5;
        const int lane = tid & 31;
        for (int r = warp; r < SM_ROWS; r += 8) {
            const int gr = m0 - 1 + r;
            const bool rowok = (unsigned)gr < (unsigned)IH;
            float4 v = make_float4(0.f, 0.f, 0.f, 0.f);
            if (rowok)
                v = *(const float4*)(xp + (size_t)gr * IW + n0 + 4 * lane);
            *(float4*)&s[r][4 + 4 * lane] = v;
            if (lane == 0) {
                float hl = 0.f, hr = 0.f;
                if (rowok) {
                    if (n0 > 0)           hl = xp[(size_t)gr * IW + n0 - 1];
                    if (n0 + TILE_X < IW) hr = xp[(size_t)gr * IW + n0 + TILE_X];
                }
                s[r][3]   = hl;   // global col n0-1
                s[r][132] = hr;   // global col n0+128
            }
        }
    }
    __syncthreads();

    const int tx = tid & 31;    // 4 input cols: n = n0 + 4*tx .. +3
    const int ty = tid >> 5;    // 4 input rows: m = m0 + 4*ty .. +3
    const int tx4 = 4 * tx;

    const float k00 = c_k[0],  k01 = c_k[1],  k02 = c_k[2],  k03 = c_k[3];
    const float k10 = c_k[4],  k11 = c_k[5],  k12 = c_k[6],  k13 = c_k[7];
    const float k20 = c_k[8],  k21 = c_k[9],  k22 = c_k[10], k23 = c_k[11];
    const float k30 = c_k[12], k31 = c_k[13], k32 = c_k[14], k33 = c_k[15];

    const int rbase = ty * 4;   // smem row of m-1 at ry=0

    float vm[6], v0[6], vp[6];
    LOADROW(vm, &s[rbase][0],     tx4);
    LOADROW(v0, &s[rbase + 1][0], tx4);

    float* obase = op + ((size_t)(m0 + ty * 4) * 2) * OW + 2 * n0 + 8 * tx;

    #pragma unroll
    for (int ry = 0; ry < 4; ry++) {
        LOADROW(vp, &s[rbase + 2 + ry][0], tx4);

        float e[8], o[8];
        #pragma unroll
        for (int j = 0; j < 4; j++) {
            const float xc = v0[1 + j], xl = v0[j], xr = v0[2 + j];
            const float mc = vm[1 + j], ml = vm[j], mr = vm[2 + j];
            const float pc = vp[1 + j], pl = vp[j], pr = vp[2 + j];
            e[2*j]   = k11*xc + k13*xl + k31*mc + k33*ml;
            e[2*j+1] = k12*xc + k10*xr + k32*mc + k30*mr;
            o[2*j]   = k21*xc + k23*xl + k01*pc + k03*pl;
            o[2*j+1] = k22*xc + k20*xr + k02*pc + k00*pr;
        }

        float* r0 = obase + (size_t)(2 * ry) * OW;
        float* r1 = r0 + OW;
        __stcs((float4*)r0,       make_float4(e[0], e[1], e[2], e[3]));
        __stcs((float4*)(r0 + 4), make_float4(e[4], e[5], e[6], e[7]));
        __stcs((float4*)r1,       make_float4(o[0], o[1], o[2], o[3]));
        __stcs((float4*)(r1 + 4), make_float4(o[4], o[5], o[6], o[7]));

        #pragma unroll
        for (int i = 0; i < 6; i++) { vm[i] = v0[i]; v0[i] = vp[i]; }
    }
}

extern "C" void kernel_launch(void* const* d_in, const int* in_sizes, int n_in,
                              void* d_out, int out_size)
{
    const float* x = (const float*)d_in[0];
    const float* k = (const float*)d_in[1];

    const int nc = in_sizes[0] / (IH * IW);   // 512 planes

    cudaMemcpyToSymbolAsync(c_k, k, 16 * sizeof(float), 0,
                            cudaMemcpyDeviceToDevice);

    dim3 grid(IW / TILE_X, IH / TILE_Y, nc);   // (2, 8, 512)
    upfirdn2x_kernel<<<grid, 256>>>(x, (float*)d_out);
}

// round 3
// speedup vs baseline: 1.4112x; 1.4112x over previous
#include <cuda_runtime.h>
#include <cstddef>

// UpsampleUpFIRDn: x (8,64,256,256) f32 -> out (8,64,512,512) f32, up=2, 4x4 FIR.
// Parity reduction (verified R1) + separable factorization (kernel is rank-1:
// outer([1,3,3,1])): k[i][j] = rho_i * gam_j with gam_j = k[0][j],
// rho_i = k[i][0]/k[0][0].
//
//  horizontal factors per input row v (window v0=x[n-1], v1=x[n], v2=x[n+1]):
//    hE = gam1*v1 + gam3*v0       (even output col 2n)
//    hO = gam2*v1 + gam0*v2       (odd  output col 2n+1)
//  vertical combine (rows a=m-1, b=m, c=m+1):
//    out[2m  ][2n]=rho1*bhE+rho3*ahE   out[2m  ][2n+1]=rho1*bhO+rho3*ahO
//    out[2m+1][2n]=rho2*bhE+rho0*chE   out[2m+1][2n+1]=rho2*bhO+rho0*chO
//
// R3: R1 tiling (64x16 input tile, 256 thr, thread = 1 col x 4 rows) with
// rolling horizontal factors (3 LDS + 12 FMA + 2 STG.64 per 4 outputs) and a
// shift-indexed vectorized tile load. Designed to fit ~30 registers.

#define IH 256
#define IW 256
#define OW 512

#define TILE_X 64
#define TILE_Y 16
#define SM_ROWS 18      // TILE_Y + 2 halo
#define SM_STRIDE 72    // 4 pad + 64 + 4 pad; %4==0 so STS.128 aligned

__constant__ float c_k[16];

__global__ __launch_bounds__(256)
void upfirdn2x_kernel(const float* __restrict__ x, float* __restrict__ out)
{
    __shared__ float s[SM_ROWS][SM_STRIDE];

    const int tid = threadIdx.x;
    const int n0  = blockIdx.x * TILE_X;
    const int m0  = blockIdx.y * TILE_Y;
    const int p   = blockIdx.z;

    const float* xp = x + (size_t)p * (IH * IW);
    float* op = out + (size_t)p * ((size_t)OW * OW);

    // ---- haloed tile load: smem col c <-> global col n0-4+c ----
    // main body: 18 rows x 16 float4 = 288 vector loads
    {
        int i = tid;
        #pragma unroll
        for (int pass = 0; pass < 2; pass++) {
            if (i < SM_ROWS * 16) {
                const int r = i >> 4;
                const int j = i & 15;
                const int gr = m0 - 1 + r;
                float4 v = make_float4(0.f, 0.f, 0.f, 0.f);
                if ((unsigned)gr < (unsigned)IH)
                    v = *(const float4*)(xp + (size_t)gr * IW + n0 + 4 * j);
                *(float4*)&s[r][4 + 4 * j] = v;
            }
            i += 256;
        }
        // halos: col 3 <-> n0-1, col 68 <-> n0+64
        if (tid < 2 * SM_ROWS) {
            const int r = tid >> 1;
            const int side = tid & 1;
            const int gr = m0 - 1 + r;
            const int gc = side ? (n0 + TILE_X) : (n0 - 1);
            float v = 0.f;
            if ((unsigned)gr < (unsigned)IH && (unsigned)gc < (unsigned)IW)
                v = xp[(size_t)gr * IW + gc];
            s[r][side ? 68 : 3] = v;
        }
    }
    __syncthreads();

    // separable coefficients (8 regs)
    const float g0 = c_k[0], g1 = c_k[1], g2 = c_k[2], g3 = c_k[3];
    const float inv = 1.0f / g0;
    const float r0 = c_k[0] * inv, r1 = c_k[4] * inv,
                r2 = c_k[8] * inv, r3 = c_k[12] * inv;

    const int tx = tid & 63;          // input col n = n0 + tx
    const int ty = tid >> 6;          // 4 input rows: m = m0 + 4*ty + ry
    const int lc = tx + 4;            // smem col of n
    const int rbase = ty * 4;         // smem row of (m-1) at ry=0

    // prologue: horizontal factors for rows m-1 and m
    float ahE, ahO, bhE, bhO;
    {
        const float a0 = s[rbase][lc-1], a1 = s[rbase][lc], a2 = s[rbase][lc+1];
        ahE = g1 * a1 + g3 * a0;
        ahO = g2 * a1 + g0 * a2;
        const float b0 = s[rbase+1][lc-1], b1 = s[rbase+1][lc], b2 = s[rbase+1][lc+1];
        bhE = g1 * b1 + g3 * b0;
        bhO = g2 * b1 + g0 * b2;
    }

    float* obase = op + ((size_t)(m0 + 4 * ty) * 2) * OW + 2 * (n0 + tx);

    #pragma unroll
    for (int ry = 0; ry < 4; ry++) {
        const float c0 = s[rbase+2+ry][lc-1];
        const float c1 = s[rbase+2+ry][lc];
        const float c2 = s[rbase+2+ry][lc+1];
        const float chE = g1 * c1 + g3 * c0;
        const float chO = g2 * c1 + g0 * c2;

        const float eE = r1 * bhE + r3 * ahE;
        const float eO = r1 * bhO + r3 * ahO;
        const float oE = r2 * bhE + r0 * chE;
        const float oO = r2 * bhO + r0 * chO;

        float* row0 = obase + (size_t)(2 * ry) * OW;
        __stcs((float2*)row0,        make_float2(eE, eO));
        __stcs((float2*)(row0 + OW), make_float2(oE, oO));

        ahE = bhE; ahO = bhO;
        bhE = chE; bhO = chO;
    }
}

extern "C" void kernel_launch(void* const* d_in, const int* in_sizes, int n_in,
                              void* d_out, int out_size)
{
    const float* x = (const float*)d_in[0];
    const float* k = (const float*)d_in[1];

    const int nc = in_sizes[0] / (IH * IW);   // 512 planes

    cudaMemcpyToSymbolAsync(c_k, k, 16 * sizeof(float), 0,
                            cudaMemcpyDeviceToDevice);

    dim3 grid(IW / TILE_X, IH / TILE_Y, nc);   // (4, 16, 512)
    upfirdn2x_kernel<<<grid, 256>>>(x, (float*)d_out);
}